// round 6
// baseline (speedup 1.0000x reference)
#include <cuda_runtime.h>

// ---------------------------------------------------------------------------
// MambaSSM: B=2, L=384, d_inner=384, d_state=384, dt_rank=384, d_conv=4
//
//   L1 (gemm_dual p0):  dt = softplus(x @ dt_w^T + dt_b) -> g_DT
//                       x_dbl = x @ B_w^T                -> g_XDBL
//   L2 (gemm_dual p1):  Bm = x_dbl @ B_w^T -> g_BM ; Cm = x_dbl @ C_w^T -> g_CM
//        + fused conv row (blockIdx.y==12): u = silu(conv(x)+cb),
//          g_SCP[b][d][l]=(dt,dt,dt*u,dt*u), g_UD[b][d][l]=u*D[d]
//   L3 (scan): CTA = 1 channel, 192 threads (6 warps), grid 768.
//       thread owns float2 of state; sc register-pipelined from smem;
//       C prefetched 2 ahead; deferred 2-level shuffle; 2-phase tile reduce.
// ---------------------------------------------------------------------------

#define LOG2E 1.4426950408889634f

__device__ float  g_DT  [768 * 384];
__device__ float  g_XDBL[768 * 384];
__device__ float  g_BM  [768 * 384];
__device__ float  g_CM  [768 * 384];
__device__ float4 g_SCP [768 * 384];   // (dt, dt, dt*u, dt*u)
__device__ float  g_UD  [768 * 384];   // u * D[d]

__device__ __forceinline__ float ex2f(float x) {
    float y;
    asm("ex2.approx.ftz.f32 %0, %1;" : "=f"(y) : "f"(x));
    return y;
}

// ---------------------------------------------------------------------------
// Dual-output tiled SGEMM (+ fused conv pass on phase 1, blockIdx.y == 12)
// ---------------------------------------------------------------------------
__global__ __launch_bounds__(256) void gemm_dual(
    const float* __restrict__ A_ext,
    const float* __restrict__ Wa,
    const float* __restrict__ Wb,
    const float* __restrict__ bias,
    const float* __restrict__ x,
    const float* __restrict__ convw,
    const float* __restrict__ convb,
    const float* __restrict__ Dvec,
    int phase)
{
    // ---- fused conv/silu/pack pass (phase 1 extra row) ----
    if (blockIdx.y == 12) {
        const int tid = threadIdx.x;
        const int chg = blockIdx.x * 64 + (tid & 63);   // 0..767
        const int seg = tid >> 6;                        // 0..3
        const int b   = chg / 384;
        const int d   = chg - b * 384;
        const int l0  = seg * 96;

        const float c0 = convw[d * 4 + 0];
        const float c1 = convw[d * 4 + 1];
        const float c2 = convw[d * 4 + 2];
        const float c3 = convw[d * 4 + 3];
        const float cb = convb[d];
        const float Dd = Dvec[d];

        const float* xb  = x    + b * 147456 + d;
        const float* dtp = g_DT + b * 147456 + d;
        float4* scp = g_SCP + (b * 384 + d) * 384;
        float*  udp = g_UD  + (b * 384 + d) * 384;

        float w0 = (l0 - 3 >= 0) ? xb[(l0 - 3) * 384] : 0.f;
        float w1 = (l0 - 2 >= 0) ? xb[(l0 - 2) * 384] : 0.f;
        float w2 = (l0 - 1 >= 0) ? xb[(l0 - 1) * 384] : 0.f;

        for (int i = 0; i < 96; ++i) {
            const int l = l0 + i;
            const float w3 = xb[l * 384];
            float v = fmaf(w0, c0, fmaf(w1, c1, fmaf(w2, c2, fmaf(w3, c3, cb))));
            const float u  = v / (1.f + ex2f(-v * LOG2E));   // silu
            const float dt = dtp[l * 384];
            const float du = dt * u;
            scp[l] = make_float4(dt, dt, du, du);
            udp[l] = u * Dd;
            w0 = w1; w1 = w2; w2 = w3;
        }
        return;
    }

    __shared__ float As[16][64];
    __shared__ float Bs[16][64];

    const float* A  = (phase == 0) ? A_ext : g_XDBL;
    float*       Ca = (phase == 0) ? g_DT  : g_BM;
    float*       Cb = (phase == 0) ? g_XDBL: g_CM;

    const int tid = threadIdx.x;
    const int m0  = blockIdx.x * 64;
    const int bn  = blockIdx.y;            // 0..11
    const bool second = (bn >= 6);
    const float* W  = second ? Wb : Wa;
    float*       Cc = second ? Cb : Ca;
    const bool doAct = (phase == 0) && !second;
    const int n0 = (second ? bn - 6 : bn) * 64;

    const int loadRow = tid >> 2;          // 0..63
    const int loadCol = (tid & 3) << 2;    // 0,4,8,12
    const float* Ap = A + (m0 + loadRow) * 384 + loadCol;
    const float* Wp = W + (n0 + loadRow) * 384 + loadCol;

    float4 aR = *(const float4*)Ap;
    float4 wR = *(const float4*)Wp;

    float acc[4][4];
#pragma unroll
    for (int i = 0; i < 4; i++)
#pragma unroll
        for (int j = 0; j < 4; j++) acc[i][j] = 0.f;

    const int tx = tid & 15;
    const int ty = tid >> 4;

    for (int kt = 0; kt < 24; ++kt) {
        As[loadCol + 0][loadRow] = aR.x;
        As[loadCol + 1][loadRow] = aR.y;
        As[loadCol + 2][loadRow] = aR.z;
        As[loadCol + 3][loadRow] = aR.w;
        Bs[loadCol + 0][loadRow] = wR.x;
        Bs[loadCol + 1][loadRow] = wR.y;
        Bs[loadCol + 2][loadRow] = wR.z;
        Bs[loadCol + 3][loadRow] = wR.w;
        __syncthreads();

        if (kt < 23) {
            aR = *(const float4*)(Ap + (kt + 1) * 16);
            wR = *(const float4*)(Wp + (kt + 1) * 16);
        }

#pragma unroll
        for (int k = 0; k < 16; ++k) {
            float4 av = *(const float4*)&As[k][ty << 2];
            float4 bv = *(const float4*)&Bs[k][tx << 2];
            float a[4] = {av.x, av.y, av.z, av.w};
            float b[4] = {bv.x, bv.y, bv.z, bv.w};
#pragma unroll
            for (int i = 0; i < 4; i++)
#pragma unroll
                for (int j = 0; j < 4; j++)
                    acc[i][j] = fmaf(a[i], b[j], acc[i][j]);
        }
        __syncthreads();
    }

#pragma unroll
    for (int i = 0; i < 4; i++) {
        const int m = m0 + (ty << 2) + i;
#pragma unroll
        for (int j = 0; j < 4; j++) {
            const int n = n0 + (tx << 2) + j;
            float v = acc[i][j];
            if (doAct) {
                v += bias[n];
                v = fmaxf(v, 0.f) + log1pf(expf(-fabsf(v)));
            }
            Cc[m * 384 + n] = v;
        }
    }
}

// ---------------------------------------------------------------------------
// SCAN v6: grid 768, block 192 (6 warps). CTA = 1 channel (b, d).
// ---------------------------------------------------------------------------
#define TL 48   // l-tile between smem reductions (384/48 = 8 tiles)

__global__ __launch_bounds__(192) void scan_kernel(
    const float* __restrict__ A_log,
    float* __restrict__ out)
{
    __shared__ float  part[TL][49];     // per-l warp partials (+pad)
    __shared__ float  part2[TL][2];
    __shared__ float4 scbuf[2][TL];     // double-buffered (dt,dt,dtu,dtu)

    const int tid  = threadIdx.x;       // 0..191
    const int lane = tid & 31;
    const int wid  = tid >> 5;          // 0..5

    const int pid = blockIdx.x;         // 0..767
    const int b   = pid >> 9 ? 1 : pid / 384;   // pid/384
    const int d   = pid - b * 384;
    const int ch  = b * 384 + d;

    // Per-thread invariants
    const float2 a = ((const float2*)(A_log + d * 384))[tid];
    const float A2x = -ex2f(a.x * LOG2E) * LOG2E;
    const float A2y = -ex2f(a.y * LOG2E) * LOG2E;
    const float2 bm = ((const float2*)(g_BM + ch * 384))[tid];
    float hx = 0.f, hy = 0.f;

    const float4* scp = g_SCP + ch * 384;
    const float*  udp = g_UD  + ch * 384;
    const float2* Cb2 = (const float2*)(g_CM + b * 147456) + tid;

    // Preload tile 0 sc
    if (tid < TL) scbuf[0][tid] = __ldg(scp + tid);
    // Prefetch C rows l=0,1
    float2 C0 = __ldg(Cb2);
    float2 C1 = __ldg(Cb2 + 192);
    __syncthreads();

    float accP = 0.f;
    float4 sc_cur = scbuf[0][0];

    for (int tile = 0; tile < 8; ++tile) {
        const int lbase = tile * TL;
        const int buf   = tile & 1;

#pragma unroll 8
        for (int i = 0; i < TL; ++i) {
            const int l = lbase + i;
            const float4 sc = sc_cur;
            sc_cur = scbuf[buf][(i < TL - 1) ? (i + 1) : (TL - 1)];
            const float2 Cv = C0;
            C0 = C1;
            const int lpf = (l + 2 < 384) ? (l + 2) : 383;
            C1 = __ldg(Cb2 + lpf * 192);

            const float e0 = ex2f(sc.x * A2x);
            hx = fmaf(e0, hx, sc.z * bm.x);
            const float e1 = ex2f(sc.y * A2y);
            hy = fmaf(e1, hy, sc.w * bm.y);
            const float acc = fmaf(hy, Cv.y, hx * Cv.x);

            if (i > 0) {   // deferred: reduce previous iteration's partial
                accP += __shfl_xor_sync(0xffffffffu, accP, 16);
                accP += __shfl_xor_sync(0xffffffffu, accP, 8);
                if (lane < 8) part[i - 1][wid * 8 + lane] = accP;
            }
            accP = acc;
        }
        accP += __shfl_xor_sync(0xffffffffu, accP, 16);
        accP += __shfl_xor_sync(0xffffffffu, accP, 8);
        if (lane < 8) part[TL - 1][wid * 8 + lane] = accP;
        accP = 0.f;
        __syncthreads();

        // Phase A: 96 threads reduce 24 partials each; 48 threads load next sc
        if (tid < 96) {
            const int li   = tid >> 1;
            const int half = tid & 1;
            const float* p = part[li] + half * 24;
            float t0 = 0.f, t1 = 0.f, t2 = 0.f, t3 = 0.f;
#pragma unroll
            for (int j = 0; j < 24; j += 4) {
                t0 += p[j]; t1 += p[j + 1]; t2 += p[j + 2]; t3 += p[j + 3];
            }
            part2[li][half] = (t0 + t1) + (t2 + t3);
        } else if (tid < 96 + TL && tile < 7) {
            scbuf[buf ^ 1][tid - 96] = __ldg(scp + lbase + TL + (tid - 96));
        }
        __syncthreads();

        // Phase B: 48 threads finalize + write
        if (tid < TL) {
            const int l = lbase + tid;
            const float y = part2[tid][0] + part2[tid][1] + __ldg(udp + l);
            out[(size_t)b * 147456 + (size_t)l * 384 + d] = y;
        }
        sc_cur = scbuf[buf ^ 1][0];
    }
}

// ---------------------------------------------------------------------------
extern "C" void kernel_launch(void* const* d_in, const int* in_sizes, int n_in,
                              void* d_out, int out_size)
{
    const float* x      = (const float*)d_in[0];
    const float* A_log  = (const float*)d_in[1];
    const float* Dvec   = (const float*)d_in[2];
    const float* dt_w   = (const float*)d_in[3];
    const float* dt_b   = (const float*)d_in[4];
    const float* B_w    = (const float*)d_in[5];
    const float* C_w    = (const float*)d_in[6];
    const float* conv_w = (const float*)d_in[7];
    const float* conv_b = (const float*)d_in[8];
    float* out = (float*)d_out;

    // GEMM1: dt (softplus) + x_dbl
    gemm_dual<<<dim3(12, 12), 256>>>(x, dt_w, B_w, dt_b,
                                     x, conv_w, conv_b, Dvec, 0);
    // GEMM2 (Bm, Cm) + fused conv/silu/pack row
    gemm_dual<<<dim3(12, 13), 256>>>(x, B_w, C_w, nullptr,
                                     x, conv_w, conv_b, Dvec, 1);
    // Scan
    scan_kernel<<<768, 192>>>(A_log, out);
}

// round 7
// speedup vs baseline: 1.2643x; 1.2643x over previous
#include <cuda_runtime.h>

// ---------------------------------------------------------------------------
// MambaSSM: B=2, L=384, d_inner=384, d_state=384, dt_rank=384, d_conv=4
//
//   GEMM1 (fused): dt = softplus(x @ dt_w^T + dt_b)   -> g_DT   [768x384]
//                  x_dbl = x @ B_w^T                  -> g_XDBL [768x384]
//   K3:            u = silu(causal_conv(x)+cb); pack per-channel scalar stream
//                  g_SC[b][d][l] = (dt, dt*u, u*D[d], 0)
//   GEMM2 (fused): Bm = x_dbl @ B_w^T                 -> g_BM   [768x384]
//                  Cm = x_dbl @ C_w^T                 -> g_CM   [768x384]
//   SCAN v5 (reverted, proven): CTA = 2 channels x 192 float2-lanes.
//   GEMM v7: 64x32 tiles, grid (12,24)=288 CTAs -> 2 CTA/SM, 16 warps/SM.
// ---------------------------------------------------------------------------

#define LOG2E 1.4426950408889634f

__device__ float  g_DT  [768 * 384];
__device__ float  g_XDBL[768 * 384];
__device__ float  g_BM  [768 * 384];
__device__ float  g_CM  [768 * 384];
__device__ float4 g_SC  [768 * 384];   // [b][d][l] : (dt, dt*u, u*D, 0)

__device__ __forceinline__ float ex2f(float x) {
    float y;
    asm("ex2.approx.ftz.f32 %0, %1;" : "=f"(y) : "f"(x));
    return y;
}

// ---------------------------------------------------------------------------
// Dual-output tiled SGEMM: C[m,n] = sum_k A[m,k] * W[n,k]
// v7: 64(M) x 32(N) tiles, 256 threads, 4x2 microtile, reg-prefetch.
// grid (12, 24): bn < 12 -> output a (Wa), bn >= 12 -> output b (Wb).
// ---------------------------------------------------------------------------
__global__ __launch_bounds__(256) void gemm_dual(
    const float* __restrict__ A_ext,
    const float* __restrict__ Wa,
    const float* __restrict__ Wb,
    const float* __restrict__ bias,
    int phase)
{
    __shared__ float As[16][64];
    __shared__ float Bs[16][32];

    const float* A  = (phase == 0) ? A_ext : g_XDBL;
    float*       Ca = (phase == 0) ? g_DT  : g_BM;
    float*       Cb = (phase == 0) ? g_XDBL: g_CM;

    const int tid = threadIdx.x;
    const int m0  = blockIdx.x * 64;
    const int bn  = blockIdx.y;            // 0..23
    const bool second = (bn >= 12);
    const float* W  = second ? Wb : Wa;
    float*       Cc = second ? Cb : Ca;
    const bool doAct = (phase == 0) && !second;
    const int n0 = (second ? bn - 12 : bn) * 32;

    const int rowA = tid >> 2;             // 0..63
    const int colA = (tid & 3) << 2;       // 0,4,8,12
    const int rowB = tid >> 3;             // 0..31
    const int colB = (tid & 7) << 1;       // 0,2,...,14
    const float* Ap = A + (m0 + rowA) * 384 + colA;
    const float* Wp = W + (n0 + rowB) * 384 + colB;

    float4 aR = *(const float4*)Ap;
    float2 wR = *(const float2*)Wp;

    float acc[4][2];
#pragma unroll
    for (int i = 0; i < 4; i++) { acc[i][0] = 0.f; acc[i][1] = 0.f; }

    const int tx = tid & 15;               // n: 2 cols each
    const int ty = tid >> 4;               // m: 4 rows each

    for (int kt = 0; kt < 24; ++kt) {
        As[colA + 0][rowA] = aR.x;
        As[colA + 1][rowA] = aR.y;
        As[colA + 2][rowA] = aR.z;
        As[colA + 3][rowA] = aR.w;
        Bs[colB + 0][rowB] = wR.x;
        Bs[colB + 1][rowB] = wR.y;
        __syncthreads();

        if (kt < 23) {
            aR = *(const float4*)(Ap + (kt + 1) * 16);
            wR = *(const float2*)(Wp + (kt + 1) * 16);
        }

#pragma unroll
        for (int k = 0; k < 16; ++k) {
            float4 av = *(const float4*)&As[k][ty << 2];
            float2 bv = *(const float2*)&Bs[k][tx << 1];
            acc[0][0] = fmaf(av.x, bv.x, acc[0][0]);
            acc[0][1] = fmaf(av.x, bv.y, acc[0][1]);
            acc[1][0] = fmaf(av.y, bv.x, acc[1][0]);
            acc[1][1] = fmaf(av.y, bv.y, acc[1][1]);
            acc[2][0] = fmaf(av.z, bv.x, acc[2][0]);
            acc[2][1] = fmaf(av.z, bv.y, acc[2][1]);
            acc[3][0] = fmaf(av.w, bv.x, acc[3][0]);
            acc[3][1] = fmaf(av.w, bv.y, acc[3][1]);
        }
        __syncthreads();
    }

#pragma unroll
    for (int i = 0; i < 4; i++) {
        const int m = m0 + (ty << 2) + i;
#pragma unroll
        for (int j = 0; j < 2; j++) {
            const int n = n0 + (tx << 1) + j;
            float v = acc[i][j];
            if (doAct) {
                v += bias[n];
                v = fmaxf(v, 0.f) + log1pf(expf(-fabsf(v)));
            }
            Cc[m * 384 + n] = v;
        }
    }
}

// ---------------------------------------------------------------------------
// K3: causal depthwise conv(4) + silu, pack scalar stream g_SC[b][d][l].
// ---------------------------------------------------------------------------
__global__ __launch_bounds__(384) void conv_sc_kernel(
    const float* __restrict__ x,
    const float* __restrict__ convw,
    const float* __restrict__ convb,
    const float* __restrict__ Dvec)
{
    const int d  = threadIdx.x;
    const int b  = blockIdx.y;
    const int l0 = blockIdx.x * 16;

    const float c0 = convw[d * 4 + 0];
    const float c1 = convw[d * 4 + 1];
    const float c2 = convw[d * 4 + 2];
    const float c3 = convw[d * 4 + 3];
    const float cb = convb[d];
    const float Dd = Dvec[d];

    const float* xb  = x    + b * 384 * 384 + d;
    const float* dtp = g_DT + b * 384 * 384 + d;
    float4*      scp = g_SC + (b * 384 + d) * 384;

    float w0 = (l0 - 3 >= 0) ? xb[(l0 - 3) * 384] : 0.f;
    float w1 = (l0 - 2 >= 0) ? xb[(l0 - 2) * 384] : 0.f;
    float w2 = (l0 - 1 >= 0) ? xb[(l0 - 1) * 384] : 0.f;

    for (int i = 0; i < 16; ++i) {
        const int l = l0 + i;
        const float w3 = xb[l * 384];
        float v = fmaf(w0, c0, fmaf(w1, c1, fmaf(w2, c2, fmaf(w3, c3, cb))));
        const float u  = v / (1.f + expf(-v));     // silu
        const float dt = dtp[l * 384];
        scp[l] = make_float4(dt, dt * u, u * Dd, 0.f);
        w0 = w1; w1 = w2; w2 = w3;
    }
}

// ---------------------------------------------------------------------------
// SCAN v5 (reverted): grid 384, block 384 (12 warps). CTA = 2 channels.
// tid 0..191 -> channel d0 (s2 = tid); tid 192..383 -> channel d0+1.
// ---------------------------------------------------------------------------
#define TL 48   // l-tile between smem reductions (384/48 = 8 tiles)

__global__ __launch_bounds__(384) void scan_kernel(
    const float* __restrict__ A_log,
    float* __restrict__ out)
{
    __shared__ float  part[2][TL][49];     // [ch][l_in_tile][48 partials + pad]
    __shared__ float4 scbuf[2][2][TL];     // [buf][ch][l_in_tile]

    const int tid  = threadIdx.x;
    const int lane = tid & 31;
    const int ch   = tid >= 192;
    const int s2   = tid - ch * 192;        // float2-state index 0..191
    const int wid6 = (tid >> 5) - ch * 6;   // warp index within channel 0..5

    const int pid   = blockIdx.x;           // 0..383
    const int b     = pid / 192;
    const int dbase = (pid - b * 192) * 2;
    const int d     = dbase + ch;

    // Per-thread invariants
    const float2 a = ((const float2*)(A_log + d * 384))[s2];
    const float A2x = -ex2f(a.x * LOG2E) * LOG2E;
    const float A2y = -ex2f(a.y * LOG2E) * LOG2E;
    const float2 bm = ((const float2*)(g_BM + (b * 384 + d) * 384))[s2];
    float hx = 0.f, hy = 0.f;

    const float4* scp0 = g_SC + (b * 384 + dbase) * 384;   // channel 0 stream
    const float2* Cb2  = (const float2*)(g_CM + b * 147456) + s2;

    // Preload tile 0 sc (threads 0..95: c = tid/48, li = tid%48)
    if (tid < 96) {
        const int c = tid / TL, li = tid - c * TL;
        scbuf[0][c][li] = __ldg(scp0 + c * 384 + li);
    }
    // Prefetch C rows l=0,1
    float2 C0 = __ldg(Cb2);
    float2 C1 = __ldg(Cb2 + 192);
    __syncthreads();

    float accP = 0.f;

    for (int tile = 0; tile < 8; ++tile) {
        const int lbase = tile * TL;
        const int buf   = tile & 1;

#pragma unroll 6
        for (int i = 0; i < TL; ++i) {
            const int l = lbase + i;
            const float4 sc = scbuf[buf][ch][i];   // LDS broadcast
            const float2 Cv = C0;
            C0 = C1;
            const int lpf = (l + 2 < 384) ? (l + 2) : 383;
            C1 = __ldg(Cb2 + lpf * 192);

            const float e0 = ex2f(sc.x * A2x);
            hx = fmaf(e0, hx, sc.y * bm.x);
            const float e1 = ex2f(sc.x * A2y);
            hy = fmaf(e1, hy, sc.y * bm.y);
            const float acc = fmaf(hy, Cv.y, hx * Cv.x);

            if (i > 0) {   // deferred: reduce previous iteration's partial
                accP += __shfl_xor_sync(0xffffffffu, accP, 16);
                accP += __shfl_xor_sync(0xffffffffu, accP, 8);
                if (lane < 8) part[ch][i - 1][wid6 * 8 + lane] = accP;
            }
            accP = acc;
        }
        // flush last iteration of the tile
        accP += __shfl_xor_sync(0xffffffffu, accP, 16);
        accP += __shfl_xor_sync(0xffffffffu, accP, 8);
        if (lane < 8) part[ch][TL - 1][wid6 * 8 + lane] = accP;
        __syncthreads();

        // Reduce + write out (tid<96); load next tile's sc (tid 96..191)
        if (tid < 96) {
            const int c  = tid / TL;
            const int li = tid - c * TL;
            const float* p = part[c][li];
            float t0 = 0.f, t1 = 0.f, t2 = 0.f, t3 = 0.f;
#pragma unroll
            for (int j = 0; j < 48; j += 4) {
                t0 += p[j]; t1 += p[j + 1]; t2 += p[j + 2]; t3 += p[j + 3];
            }
            const int l = lbase + li;
            float y = (t0 + t1) + (t2 + t3);
            y += scbuf[buf][c][li].z;              // u*D term
            out[(size_t)b * 147456 + (size_t)l * 384 + dbase + c] = y;
        } else if (tid < 192 && tile < 7) {
            const int t2i = tid - 96;
            const int c = t2i / TL, li = t2i - c * TL;
            scbuf[buf ^ 1][c][li] = __ldg(scp0 + c * 384 + lbase + TL + li);
        }
        __syncthreads();
    }
}

// ---------------------------------------------------------------------------
extern "C" void kernel_launch(void* const* d_in, const int* in_sizes, int n_in,
                              void* d_out, int out_size)
{
    const float* x      = (const float*)d_in[0];
    const float* A_log  = (const float*)d_in[1];
    const float* Dvec   = (const float*)d_in[2];
    const float* dt_w   = (const float*)d_in[3];
    const float* dt_b   = (const float*)d_in[4];
    const float* B_w    = (const float*)d_in[5];
    const float* C_w    = (const float*)d_in[6];
    const float* conv_w = (const float*)d_in[7];
    const float* conv_b = (const float*)d_in[8];
    float* out = (float*)d_out;

    gemm_dual<<<dim3(12, 24), 256>>>(x, dt_w, B_w, dt_b, 0);
    conv_sc_kernel<<<dim3(24, 2), 384>>>(x, conv_w, conv_b, Dvec);
    gemm_dual<<<dim3(12, 24), 256>>>(x, B_w, C_w, nullptr, 1);
    scan_kernel<<<384, 384>>>(A_log, out);
}

// round 8
// speedup vs baseline: 1.3679x; 1.0819x over previous
#include <cuda_runtime.h>

// ---------------------------------------------------------------------------
// MambaSSM: B=2, L=384, d_inner=384, d_state=384, dt_rank=384, d_conv=4
//
//   GEMM1 (fused): dt = softplus(x @ dt_w^T + dt_b)   -> g_DT   [768x384]
//                  x_dbl = x @ B_w^T                  -> g_XDBL [768x384]
//   K3:            u = silu(causal_conv(x)+cb); pack per-channel scalar stream
//                  g_SC[b][d][l] = (dt, dt*u, u*D[d], 0)
//   GEMM2 (fused): Bm = x_dbl @ B_w^T                 -> g_BM   [768x384]
//                  Cm = x_dbl @ C_w^T                 -> g_CM   [768x384]
//   SCAN v8: CTA = 2 channels x 192 float2-lanes = 384 threads, grid 384.
//     NO per-step shuffles: every lane stores its partial (STS, conflict-free);
//     tile TL=24; reduce phase uses all 384 threads (8 per (ch,l), oct-shfl).
//   GEMM: reverted to proven v5 64x64 tiles, grid (12,12).
// ---------------------------------------------------------------------------

#define LOG2E 1.4426950408889634f

__device__ float  g_DT  [768 * 384];
__device__ float  g_XDBL[768 * 384];
__device__ float  g_BM  [768 * 384];
__device__ float  g_CM  [768 * 384];
__device__ float4 g_SC  [768 * 384];   // [b][d][l] : (dt, dt*u, u*D, 0)

__device__ __forceinline__ float ex2f(float x) {
    float y;
    asm("ex2.approx.ftz.f32 %0, %1;" : "=f"(y) : "f"(x));
    return y;
}

// ---------------------------------------------------------------------------
// Dual-output tiled SGEMM (v5, proven): 64x64 tiles, grid (12,12).
// ---------------------------------------------------------------------------
__global__ __launch_bounds__(256) void gemm_dual(
    const float* __restrict__ A_ext,
    const float* __restrict__ Wa,
    const float* __restrict__ Wb,
    const float* __restrict__ bias,
    int phase)
{
    __shared__ float As[16][64];
    __shared__ float Bs[16][64];

    const float* A  = (phase == 0) ? A_ext : g_XDBL;
    float*       Ca = (phase == 0) ? g_DT  : g_BM;
    float*       Cb = (phase == 0) ? g_XDBL: g_CM;

    const int tid = threadIdx.x;
    const int m0  = blockIdx.x * 64;
    const int bn  = blockIdx.y;            // 0..11
    const bool second = (bn >= 6);
    const float* W  = second ? Wb : Wa;
    float*       Cc = second ? Cb : Ca;
    const bool doAct = (phase == 0) && !second;
    const int n0 = (second ? bn - 6 : bn) * 64;

    const int loadRow = tid >> 2;          // 0..63
    const int loadCol = (tid & 3) << 2;    // 0,4,8,12
    const float* Ap = A + (m0 + loadRow) * 384 + loadCol;
    const float* Wp = W + (n0 + loadRow) * 384 + loadCol;

    float4 aR = *(const float4*)Ap;
    float4 wR = *(const float4*)Wp;

    float acc[4][4];
#pragma unroll
    for (int i = 0; i < 4; i++)
#pragma unroll
        for (int j = 0; j < 4; j++) acc[i][j] = 0.f;

    const int tx = tid & 15;
    const int ty = tid >> 4;

    for (int kt = 0; kt < 24; ++kt) {
        As[loadCol + 0][loadRow] = aR.x;
        As[loadCol + 1][loadRow] = aR.y;
        As[loadCol + 2][loadRow] = aR.z;
        As[loadCol + 3][loadRow] = aR.w;
        Bs[loadCol + 0][loadRow] = wR.x;
        Bs[loadCol + 1][loadRow] = wR.y;
        Bs[loadCol + 2][loadRow] = wR.z;
        Bs[loadCol + 3][loadRow] = wR.w;
        __syncthreads();

        if (kt < 23) {
            aR = *(const float4*)(Ap + (kt + 1) * 16);
            wR = *(const float4*)(Wp + (kt + 1) * 16);
        }

#pragma unroll
        for (int k = 0; k < 16; ++k) {
            float4 av = *(const float4*)&As[k][ty << 2];
            float4 bv = *(const float4*)&Bs[k][tx << 2];
            float a[4] = {av.x, av.y, av.z, av.w};
            float b[4] = {bv.x, bv.y, bv.z, bv.w};
#pragma unroll
            for (int i = 0; i < 4; i++)
#pragma unroll
                for (int j = 0; j < 4; j++)
                    acc[i][j] = fmaf(a[i], b[j], acc[i][j]);
        }
        __syncthreads();
    }

#pragma unroll
    for (int i = 0; i < 4; i++) {
        const int m = m0 + (ty << 2) + i;
#pragma unroll
        for (int j = 0; j < 4; j++) {
            const int n = n0 + (tx << 2) + j;
            float v = acc[i][j];
            if (doAct) {
                v += bias[n];
                v = fmaxf(v, 0.f) + log1pf(expf(-fabsf(v)));
            }
            Cc[m * 384 + n] = v;
        }
    }
}

// ---------------------------------------------------------------------------
// K3: causal depthwise conv(4) + silu, pack scalar stream g_SC[b][d][l].
// ---------------------------------------------------------------------------
__global__ __launch_bounds__(384) void conv_sc_kernel(
    const float* __restrict__ x,
    const float* __restrict__ convw,
    const float* __restrict__ convb,
    const float* __restrict__ Dvec)
{
    const int d  = threadIdx.x;
    const int b  = blockIdx.y;
    const int l0 = blockIdx.x * 16;

    const float c0 = convw[d * 4 + 0];
    const float c1 = convw[d * 4 + 1];
    const float c2 = convw[d * 4 + 2];
    const float c3 = convw[d * 4 + 3];
    const float cb = convb[d];
    const float Dd = Dvec[d];

    const float* xb  = x    + b * 384 * 384 + d;
    const float* dtp = g_DT + b * 384 * 384 + d;
    float4*      scp = g_SC + (b * 384 + d) * 384;

    float w0 = (l0 - 3 >= 0) ? xb[(l0 - 3) * 384] : 0.f;
    float w1 = (l0 - 2 >= 0) ? xb[(l0 - 2) * 384] : 0.f;
    float w2 = (l0 - 1 >= 0) ? xb[(l0 - 1) * 384] : 0.f;

    for (int i = 0; i < 16; ++i) {
        const int l = l0 + i;
        const float w3 = xb[l * 384];
        float v = fmaf(w0, c0, fmaf(w1, c1, fmaf(w2, c2, fmaf(w3, c3, cb))));
        const float u  = v / (1.f + expf(-v));     // silu
        const float dt = dtp[l * 384];
        scp[l] = make_float4(dt, dt * u, u * Dd, 0.f);
        w0 = w1; w1 = w2; w2 = w3;
    }
}

// ---------------------------------------------------------------------------
// SCAN v8: grid 384, block 384. CTA = 2 channels of one batch.
// tid 0..191 -> channel d0 (s2 = tid); tid 192..383 -> channel d0+1.
// Inner loop: no shuffles; part[i][tid] = lane partial (STS).
// Reduce: 8 threads per (ch,l) pair, 6x LDS.128 + oct shuffle; sub==0 writes.
// ---------------------------------------------------------------------------
#define TL 24   // l-tile between smem reductions (384/24 = 16 tiles)

__global__ __launch_bounds__(384) void scan_kernel(
    const float* __restrict__ A_log,
    float* __restrict__ out)
{
    __shared__ float  part[TL][392];       // [l_in_tile][384 lane partials + pad]
    __shared__ float4 scbuf[2][2][TL];     // [buf][ch][l_in_tile]

    const int tid  = threadIdx.x;
    const int ch   = tid >= 192;
    const int s2   = tid - ch * 192;        // float2-state index 0..191

    const int pid   = blockIdx.x;           // 0..383
    const int b     = pid / 192;
    const int dbase = (pid - b * 192) * 2;
    const int d     = dbase + ch;

    // Per-thread invariants
    const float2 a = ((const float2*)(A_log + d * 384))[s2];
    const float A2x = -ex2f(a.x * LOG2E) * LOG2E;
    const float A2y = -ex2f(a.y * LOG2E) * LOG2E;
    const float2 bm = ((const float2*)(g_BM + (b * 384 + d) * 384))[s2];
    float hx = 0.f, hy = 0.f;

    const float4* scp0 = g_SC + (b * 384 + dbase) * 384;   // channel-0 stream
    const float2* Cb2  = (const float2*)(g_CM + b * 147456) + s2;

    // Preload tile 0 sc (threads 0..47: c = tid/24, li = tid%24)
    if (tid < 2 * TL)
        scbuf[0][tid / TL][tid % TL] = __ldg(scp0 + (tid / TL) * 384 + (tid % TL));
    // Prefetch C rows l=0,1
    float2 C0 = __ldg(Cb2);
    float2 C1 = __ldg(Cb2 + 192);
    __syncthreads();

    // Reduce-phase roles
    const int pair = tid >> 3;            // 0..47 : (chp, lip)
    const int sub  = tid & 7;
    const int chp  = pair / TL;
    const int lip  = pair - chp * TL;
    const float4* redp = (const float4*)(&part[lip][chp * 192 + sub * 24]);

    for (int tile = 0; tile < 16; ++tile) {
        const int lbase = tile * TL;
        const int buf   = tile & 1;

#pragma unroll 8
        for (int i = 0; i < TL; ++i) {
            const int l = lbase + i;
            const float4 sc = scbuf[buf][ch][i];   // LDS broadcast
            const float2 Cv = C0;
            C0 = C1;
            const int lpf = (l + 2 < 384) ? (l + 2) : 383;
            C1 = __ldg(Cb2 + lpf * 192);

            const float e0 = ex2f(sc.x * A2x);
            hx = fmaf(e0, hx, sc.y * bm.x);
            const float e1 = ex2f(sc.x * A2y);
            hy = fmaf(e1, hy, sc.y * bm.y);
            part[i][tid] = fmaf(hy, Cv.y, hx * Cv.x);
        }
        __syncthreads();

        // Prefetch next tile's sc into registers (48 threads)
        float4 scn;
        if (tid < 2 * TL && tile < 15)
            scn = __ldg(scp0 + (tid / TL) * 384 + lbase + TL + (tid / TL == 0 ? tid : tid - TL));

        // Reduce: 8 threads per (ch,l); each sums 24 values (6 x LDS.128)
        float4 r0 = redp[0], r1 = redp[1], r2 = redp[2];
        float4 r3 = redp[3], r4 = redp[4], r5 = redp[5];
        float t0 = (r0.x + r0.y) + (r0.z + r0.w);
        float t1 = (r1.x + r1.y) + (r1.z + r1.w);
        float t2 = (r2.x + r2.y) + (r2.z + r2.w);
        float t3 = (r3.x + r3.y) + (r3.z + r3.w);
        float t4 = (r4.x + r4.y) + (r4.z + r4.w);
        float t5 = (r5.x + r5.y) + (r5.z + r5.w);
        float v = ((t0 + t1) + (t2 + t3)) + (t4 + t5);
        v += __shfl_xor_sync(0xffffffffu, v, 4);
        v += __shfl_xor_sync(0xffffffffu, v, 2);
        v += __shfl_xor_sync(0xffffffffu, v, 1);
        if (sub == 0) {
            const int l = lbase + lip;
            out[(size_t)b * 147456 + (size_t)l * 384 + dbase + chp] =
                v + scbuf[buf][chp][lip].z;        // + u*D term
        }
        if (tid < 2 * TL && tile < 15)
            scbuf[buf ^ 1][tid / TL][tid / TL == 0 ? tid : tid - TL] = scn;
        __syncthreads();
    }
}

// ---------------------------------------------------------------------------
extern "C" void kernel_launch(void* const* d_in, const int* in_sizes, int n_in,
                              void* d_out, int out_size)
{
    const float* x      = (const float*)d_in[0];
    const float* A_log  = (const float*)d_in[1];
    const float* Dvec   = (const float*)d_in[2];
    const float* dt_w   = (const float*)d_in[3];
    const float* dt_b   = (const float*)d_in[4];
    const float* B_w    = (const float*)d_in[5];
    const float* C_w    = (const float*)d_in[6];
    const float* conv_w = (const float*)d_in[7];
    const float* conv_b = (const float*)d_in[8];
    float* out = (float*)d_out;

    gemm_dual<<<dim3(12, 12), 256>>>(x, dt_w, B_w, dt_b, 0);
    conv_sc_kernel<<<dim3(24, 2), 384>>>(x, conv_w, conv_b, Dvec);
    gemm_dual<<<dim3(12, 12), 256>>>(x, B_w, C_w, nullptr, 1);
    scan_kernel<<<384, 384>>>(A_log, out);
}